// round 16
// baseline (speedup 1.0000x reference)
#include <cuda_runtime.h>
#include <cuda_bf16.h>
#include <cstdint>

// ----------------------------------------------------------------------------
// OpenLSTM: HIDDEN=16, PROJ=2, INPUT=2. B=64, T=8192, nstep=4096.
//
// Phase 2 (R16): CONTRACTION SPLITTING, K=24 segments/batch, WARMUP=48.
// 128 scan blocks x 12 warps (3 scan warps/SMSP). R15 measured the REDUX
// unit as the binding pipe (~40 cyc/SMSP rt, 2 redux/step). R16 uses a
// HYBRID reduction: h0 via REDUX.SUM.S32 on magic fixed point (unchanged),
// h1 via same-warp smem gather (high lanes STS p1; 4x LDS.128 + f32x2 tree,
// the R3-validated no-syncwarp pattern) - moving half the reduction load
// onto the LSU pipe.
// ----------------------------------------------------------------------------

#define HIDDEN 16
#define BATCH  64
#define KSEG 24                   // segments per batch
#define SEG_PER_BLOCK 12          // warps per scan block
#define P2_BLOCKS (BATCH * KSEG / SEG_PER_BLOCK)   // 128
#define P1_BLOCKS 128             // 2 per batch, grid-stride over t
#define TPB 384
#define CHUNK 8
#define WARMUP 48                 // contraction warm-up steps

#define MAGICF  12582912.0f       // 2^23 + 2^22
#define BASEI   0x4B400000        // bit pattern of MAGICF
#define M2BITS  0x2E800000        // BASEI - DEBIAS (filler-lane addend bits)
#define FIXS    524288.0f         // 2^19
#define INV_FIXS (1.0f / 524288.0f)

// --- activations -------------------------------------------------------------
__device__ __forceinline__ float tanh_mufu(float x) {
    float y;
    asm("tanh.approx.f32 %0, %1;" : "=f"(y) : "f"(x));
    return y;
}

__device__ __forceinline__ int redux_s32(int v) {
    int r;
    asm volatile("redux.sync.add.s32 %0, %1, 0xFFFFFFFF;" : "=r"(r) : "r"(v));
    return r;
}

__device__ __forceinline__ unsigned long long addf32x2(unsigned long long a,
                                                       unsigned long long b) {
    unsigned long long r;
    asm("add.rn.f32x2 %0, %1, %2;" : "=l"(r) : "l"(a), "l"(b));
    return r;
}

// same-warp smem gather-sum of 16 floats at addr_ld (64B): 4x LDS.128 +
// packed f32x2 tree. Caller must have STS'd the values earlier in program
// order (in-order LSU; validated in R3 without syncwarp).
__device__ __forceinline__ float gather_sum16(uint32_t addr_ld) {
    unsigned long long q[8];
#pragma unroll
    for (int k = 0; k < 4; k++) {
        asm volatile("ld.shared.v2.u64 {%0, %1}, [%2];"
                     : "=l"(q[2*k]), "=l"(q[2*k+1])
                     : "r"(addr_ld + 16u * k) : "memory");
    }
    unsigned long long t0 = addf32x2(q[0], q[1]);
    unsigned long long t1 = addf32x2(q[2], q[3]);
    unsigned long long t2 = addf32x2(q[4], q[5]);
    unsigned long long t3 = addf32x2(q[6], q[7]);
    t0 = addf32x2(t0, t1);
    t2 = addf32x2(t2, t3);
    t0 = addf32x2(t0, t2);
    float lo, hi;
    asm("mov.b64 {%0, %1}, %2;" : "=f"(lo), "=f"(hi) : "l"(t0));
    return lo + hi;
}

// ----------------------------------------------------------------------------
__global__ void __launch_bounds__(TPB, 1)
lstm_fused(const float* __restrict__ u_train,
           const float* __restrict__ y_train,
           const float* __restrict__ W_ih,
           const float* __restrict__ W_hh,
           const float* __restrict__ b_ih,
           const float* __restrict__ b_hh,
           const float* __restrict__ W_hr,
           const int*   __restrict__ nstep_p,
           float* __restrict__ out, int T)
{
    const int nstep = nstep_p ? *nstep_p : (T >> 1);

    if (blockIdx.x >= P2_BLOCKS) {
        // ================= PHASE 1: parallel prefix ==========================
        __shared__ float s_wih[8 * HIDDEN];
        __shared__ float s_b[4 * HIDDEN];
        __shared__ float s_whr[2 * HIDDEN];
        const int tid = threadIdx.x;
        if (tid < 8 * HIDDEN) s_wih[tid] = W_ih[tid];
        if (tid < 4 * HIDDEN) s_b[tid]   = b_ih[tid] + b_hh[tid];
        if (tid < 2 * HIDDEN) s_whr[tid] = W_hr[tid];
        __syncthreads();

        const int pb   = blockIdx.x - P2_BLOCKS;   // 0..P1_BLOCKS-1
        const int b    = pb >> 1;                  // batch
        const int half = pb & 1;                   // even/odd half of t-range

        for (int t = half * TPB + tid; t < nstep; t += 2 * TPB) {
            const float2 x = *reinterpret_cast<const float2*>(
                y_train + ((size_t)b * T + t) * 2);

            float y0 = 0.0f, y1 = 0.0f;
#pragma unroll
            for (int j = 0; j < HIDDEN; j++) {
                const int ri = j, rg = 32 + j, ro = 48 + j;
                float vi = fmaf(s_wih[2*ri], x.x, fmaf(s_wih[2*ri+1], x.y, s_b[ri]));
                float vg = fmaf(s_wih[2*rg], x.x, fmaf(s_wih[2*rg+1], x.y, s_b[rg]));
                float vo = fmaf(s_wih[2*ro], x.x, fmaf(s_wih[2*ro+1], x.y, s_b[ro]));
                float si = fmaf(0.5f, tanh_mufu(0.5f * vi), 0.5f);
                float so = fmaf(0.5f, tanh_mufu(0.5f * vo), 0.5f);
                float c  = si * tanh_mufu(vg);
                float z  = so * tanh_mufu(c);
                y0 = fmaf(z, s_whr[j],          y0);
                y1 = fmaf(z, s_whr[HIDDEN + j], y1);
            }
            *reinterpret_cast<float2*>(out + ((size_t)b * T + t) * 2) =
                make_float2(y0, y1);
        }
        return;
    }

    // ==================== PHASE 2: sequential scan ===========================
    __shared__ __align__(16) float s_red[SEG_PER_BLOCK][HIDDEN];

    const int lane  = threadIdx.x & 31;
    const int wid   = threadIdx.x >> 5;            // 0..11
    const int batch = blockIdx.x >> 1;
    const int seg   = (blockIdx.x & 1) * SEG_PER_BLOCK + wid;   // 0..23
    const bool low  = (lane < 16);        // low half -> h0, high half -> h1
    const int j     = lane & 15;          // hidden unit index (0..15)

    uint32_t sbase;
    asm("{ .reg .u64 t; cvta.to.shared.u64 t, %1; cvt.u32.u64 %0, t; }"
        : "=r"(sbase) : "l"(&s_red[wid][0]));
    const uint32_t addr_st = sbase + (uint32_t)j * 4;   // high lanes store p1

    float wih0[4], wih1[4], whh0s[4], whh1r[4], bs[4];
#pragma unroll
    for (int g = 0; g < 4; g++) {
        const int r = g * HIDDEN + j;
        const float sc = (g == 2) ? 1.0f : 0.5f;   // g-gate uses raw tanh
        wih0[g]  = sc * __ldg(W_ih + 2 * r);
        wih1[g]  = sc * __ldg(W_ih + 2 * r + 1);
        whh0s[g] = sc * __ldg(W_hh + 2 * r)     * INV_FIXS;   // consumes f0
        whh1r[g] = sc * __ldg(W_hh + 2 * r + 1);              // consumes h1
        bs[g]    = sc * (__ldg(b_ih + r) + __ldg(b_hh + r))
                   - whh0s[g] * MAGICF;
    }
    // h0 path (fixed point, redux): w20 = 0.5*whr0*S on low half, 0 on high
    const float w20 = low ? 0.5f * __ldg(W_hr + j) * FIXS : 0.0f;
    const float mg0 = (lane == 16) ? __int_as_float(M2BITS) : MAGICF;
    // h1 path (float, smem): only high lanes store; w21h = 0.5*whr1
    const float w21h = 0.5f * __ldg(W_hr + HIDDEN + j);

    const size_t base = (size_t)batch * T;
    const int steps = T - nstep;

    // ---- segment boundaries (balanced): X = work per warp ------------------
    int X = (steps + (KSEG - 1) * WARMUP + KSEG - 1) / KSEG;
    if (X > steps) X = steps;
    int out_start = (seg == 0) ? 0 : X + (seg - 1) * (X - WARMUP);
    int out_end   = (seg == KSEG - 1) ? steps : X + seg * (X - WARMUP);
    if (out_start > steps) out_start = steps;
    if (out_end   > steps) out_end   = steps;
    if (out_end   < out_start) out_end = out_start;
    int s_begin = (seg == 0) ? 0 : out_start - WARMUP;
    if (s_begin < 0) s_begin = 0;

    float c, halfc, f0, h1;   // f0 = MAGIC + h0*S (biased); h1 plain float
    if (seg == 0) {
        // exact seed from step t = nstep-1 (x from y_train, h_prev = 0)
        const float2 x = *reinterpret_cast<const float2*>(
            y_train + (base + nstep - 1) * 2);
        float rb[4];
#pragma unroll
        for (int g = 0; g < 4; g++)
            rb[g] = bs[g] + whh0s[g] * MAGICF;
        float vi = fmaf(wih0[0], x.x, fmaf(wih1[0], x.y, rb[0]));
        float vg = fmaf(wih0[2], x.x, fmaf(wih1[2], x.y, rb[2]));
        float vo = fmaf(wih0[3], x.x, fmaf(wih1[3], x.y, rb[3]));
        float si = fmaf(0.5f, tanh_mufu(vi), 0.5f);
        float to = tanh_mufu(vo);
        c = si * tanh_mufu(vg);
        halfc = 0.5f * c;
        const float tc = tanh_mufu(c);
        const float so0 = fmaf(to, w20, w20);
        const int q0 = __float_as_int(fmaf(so0, tc, mg0));
        const float so1 = fmaf(to, w21h, w21h);
        const float p1 = so1 * tc;
        if (lane >= 16)
            asm volatile("st.shared.f32 [%0], %1;" :: "r"(addr_st), "f"(p1)
                         : "memory");
        f0 = __int_as_float(redux_s32(q0));
        h1 = gather_sum16(sbase);
    } else {
        c = 0.0f; halfc = 0.0f;
        f0 = MAGICF; h1 = 0.0f;   // h = 0 (f0 in magic-biased form)
    }

    const float2* __restrict__ xp =
        reinterpret_cast<const float2*>(u_train) + base + nstep;
    float2* __restrict__ op = reinterpret_cast<float2*>(out) + base + nstep;

#define LSTM_STEP(S_IDX, X_, DO_STORE)                                         \
    {                                                                          \
        const float2 x_ = (X_);                                                \
        float xb0 = fmaf(wih0[0], x_.x, fmaf(wih1[0], x_.y, bs[0]));           \
        float xb1 = fmaf(wih0[1], x_.x, fmaf(wih1[1], x_.y, bs[1]));           \
        float xb2 = fmaf(wih0[2], x_.x, fmaf(wih1[2], x_.y, bs[2]));           \
        float xb3 = fmaf(wih0[3], x_.x, fmaf(wih1[3], x_.y, bs[3]));           \
        float v0 = fmaf(whh1r[0], h1, fmaf(whh0s[0], f0, xb0));                \
        float v1 = fmaf(whh1r[1], h1, fmaf(whh0s[1], f0, xb1));                \
        float v2 = fmaf(whh1r[2], h1, fmaf(whh0s[2], f0, xb2));                \
        float v3 = fmaf(whh1r[3], h1, fmaf(whh0s[3], f0, xb3));                \
        const float ti = tanh_mufu(v0);                                        \
        const float tg = tanh_mufu(v2);                                        \
        const float tf = tanh_mufu(v1);                                        \
        const float to = tanh_mufu(v3);                                        \
        const float si = fmaf(0.5f, ti, 0.5f);                                 \
        const float ig = si * tg;                                              \
        const float inner = halfc + ig;                                        \
        c = fmaf(tf, halfc, inner);                                            \
        halfc = 0.5f * c;                                                      \
        const float tc = tanh_mufu(c);                                         \
        const float so0 = fmaf(to, w20, w20);                                  \
        const float so1 = fmaf(to, w21h, w21h);                                \
        const int q0 = __float_as_int(fmaf(so0, tc, mg0));                     \
        const float p1 = so1 * tc;                                             \
        if (lane >= 16)                                                        \
            asm volatile("st.shared.f32 [%0], %1;" :: "r"(addr_st), "f"(p1)    \
                         : "memory");                                          \
        f0 = __int_as_float(redux_s32(q0));                                    \
        h1 = gather_sum16(sbase);                                              \
        if ((DO_STORE) && lane == 0)                                           \
            op[S_IDX] = make_float2((f0 - MAGICF) * INV_FIXS, h1);             \
    }

    int s = s_begin;
    // ---- warm-up region (no stores) ----------------------------------------
    for (; s + CHUNK <= out_start; s += CHUNK) {
        float2 xr[CHUNK];
#pragma unroll
        for (int k = 0; k < CHUNK; k++) xr[k] = xp[s + k];
#pragma unroll
        for (int k = 0; k < CHUNK; k++) {
            LSTM_STEP(s + k, xr[k], 0);
        }
    }
    for (; s < out_start; s++) {
        const float2 xs = xp[s];
        LSTM_STEP(s, xs, 0);
    }
    // ---- output region ------------------------------------------------------
    for (; s + CHUNK <= out_end; s += CHUNK) {
        const float2* pfa = xp + min(s + 4 * CHUNK, out_end - 1);
        asm volatile("prefetch.global.L1 [%0];" :: "l"(pfa));
        float2 xr[CHUNK];
#pragma unroll
        for (int k = 0; k < CHUNK; k++) xr[k] = xp[s + k];
#pragma unroll
        for (int k = 0; k < CHUNK; k++) {
            LSTM_STEP(s + k, xr[k], 1);
        }
    }
    for (; s < out_end; s++) {
        const float2 xs = xp[s];
        LSTM_STEP(s, xs, 1);
    }
#undef LSTM_STEP
}

// ----------------------------------------------------------------------------
extern "C" void kernel_launch(void* const* d_in, const int* in_sizes, int n_in,
                              void* d_out, int out_size)
{
    const float* u_train = (const float*)d_in[0];
    const float* y_train = (const float*)d_in[1];
    const float* W_ih    = (const float*)d_in[2];
    const float* W_hh    = (const float*)d_in[3];
    const float* b_ih    = (const float*)d_in[4];
    const float* b_hh    = (const float*)d_in[5];
    const float* W_hr    = (const float*)d_in[6];
    const int*   nstep_p = (n_in >= 8) ? (const int*)d_in[7] : nullptr;

    const int B = BATCH;
    const int T = in_sizes[0] / (B * 2);           // u_train is (B, T, 2)
    float* out = (float*)d_out;

    const int grid = P2_BLOCKS + P1_BLOCKS;        // 256 blocks

    lstm_fused<<<grid, TPB>>>(u_train, y_train, W_ih, W_hh, b_ih, b_hh,
                              W_hr, nstep_p, out, T);
}